// round 13
// baseline (speedup 1.0000x reference)
#include <cuda_runtime.h>
#include <cuda_fp16.h>
#include <cstdint>
#include <cstddef>

// Problem dims
#define TOKENS_N 8192
#define IN_F     4096
#define OUT_F    4096

// GEMM tiling: CTA 128x128, warp 64x32, BK=64 halves (128B/row)
#define BM      128
#define BN      128
#define BK      64
#define STAGES  3
#define NCHUNK  (IN_F / BK)            // 64

// smem: 128B rows with XOR swizzle (seg ^= row&7) -> conflict-free for both
// cp.async 16B stores and ldmatrix 8-row phases.
#define ROW_BYTES    128
#define A_TILE_BYTES (BM * ROW_BYTES)                 // 16384
#define B_TILE_BYTES (BN * ROW_BYTES)                 // 16384
#define STAGE_BYTES  (A_TILE_BYTES + B_TILE_BYTES)    // 32768
#define SMEM_BYTES   (STAGES * STAGE_BYTES)           // 98304 -> 2 CTAs/SM

// Pre-converted operands (device globals: allowed scratch)
__device__ __half g_X [(size_t)TOKENS_N * IN_F];   // 64 MB
__device__ __half g_Wh[(size_t)OUT_F   * IN_F];    // 32 MB

#define GX_BLOCKS ((unsigned)(((size_t)TOKENS_N * IN_F / 8) / 256))   // 16384
#define GW_BLOCKS ((unsigned)(((size_t)OUT_F   * IN_F / 8) / 256))    // 8192

// ---------------------------------------------------------------------------
// helpers
// ---------------------------------------------------------------------------
__device__ __forceinline__ uint32_t smem_u32(const void* p) {
    uint32_t a;
    asm("{ .reg .u64 t; cvta.to.shared.u64 t, %1; cvt.u32.u64 %0, t; }"
        : "=r"(a) : "l"(p));
    return a;
}

__device__ __forceinline__ void cp_async16(uint32_t dst, const void* src) {
    asm volatile("cp.async.cg.shared.global [%0], [%1], 16;" :: "r"(dst), "l"(src));
}
#define CP_COMMIT() asm volatile("cp.async.commit_group;" ::: "memory")
#define CP_WAIT(n)  asm volatile("cp.async.wait_group %0;" :: "n"(n) : "memory")

__device__ __forceinline__ void ldsm_x4(uint32_t* r, uint32_t addr) {
    asm volatile("ldmatrix.sync.aligned.m8n8.x4.shared.b16 {%0,%1,%2,%3}, [%4];"
        : "=r"(r[0]), "=r"(r[1]), "=r"(r[2]), "=r"(r[3]) : "r"(addr));
}

__device__ __forceinline__ void mma_f16(float* c, const uint32_t* a,
                                        uint32_t b0, uint32_t b1) {
    asm volatile(
        "mma.sync.aligned.m16n8k16.row.col.f32.f16.f16.f32 "
        "{%0,%1,%2,%3}, {%4,%5,%6,%7}, {%8,%9}, {%0,%1,%2,%3};"
        : "+f"(c[0]), "+f"(c[1]), "+f"(c[2]), "+f"(c[3])
        : "r"(a[0]), "r"(a[1]), "r"(a[2]), "r"(a[3]), "r"(b0), "r"(b1));
}

__device__ __forceinline__ uint32_t h2u(__half2 h) {
    return *reinterpret_cast<uint32_t*>(&h);
}

// ---------------------------------------------------------------------------
// Kernel 1 (merged): blocks [0, GX_BLOCKS) convert X fp32->fp16;
// blocks [GX_BLOCKS, ...) gather+convert W. Both DRAM-bound; overlapped.
// ---------------------------------------------------------------------------
__global__ void __launch_bounds__(256)
prep_operands(const float* __restrict__ x, const int* __restrict__ idx,
              const float* __restrict__ w) {
    unsigned b = blockIdx.x;
    if (b < GX_BLOCKS) {
        size_t i = (size_t)b * 256 + threadIdx.x;
        const float4* p = reinterpret_cast<const float4*>(x) + 2 * i;
        float4 a = p[0], c = p[1];
        uint4 o;
        o.x = h2u(__floats2half2_rn(a.x, a.y));
        o.y = h2u(__floats2half2_rn(a.z, a.w));
        o.z = h2u(__floats2half2_rn(c.x, c.y));
        o.w = h2u(__floats2half2_rn(c.z, c.w));
        reinterpret_cast<uint4*>(g_X)[i] = o;
    } else {
        size_t i = (size_t)(b - GX_BLOCKS) * 256 + threadIdx.x;
        const int4* ip = reinterpret_cast<const int4*>(idx) + 2 * i;
        int4 v0 = ip[0], v1 = ip[1];
        uint4 o;
        o.x = h2u(__floats2half2_rn(__ldg(w + v0.x), __ldg(w + v0.y)));
        o.y = h2u(__floats2half2_rn(__ldg(w + v0.z), __ldg(w + v0.w)));
        o.z = h2u(__floats2half2_rn(__ldg(w + v1.x), __ldg(w + v1.y)));
        o.w = h2u(__floats2half2_rn(__ldg(w + v1.z), __ldg(w + v1.w)));
        reinterpret_cast<uint4*>(g_Wh)[i] = o;
    }
}

// ---------------------------------------------------------------------------
// Kernel 2: fp16 mma.sync GEMM  Out[m,n] = sum_k X[m,k]*W[n,k] + bias[n]
// 256 threads = 8 warps, 2(M) x 4(N), warp tile 64x32.
// 3-stage cp.async pipeline; A fragments double-buffered, B single-buffered
// (keeps regs under the 128 cap for 2 CTAs/SM -- no spills).
// ---------------------------------------------------------------------------
extern "C" __global__ void __launch_bounds__(256, 2)
hashed_gemm(const float* __restrict__ bias, float* __restrict__ Out) {
    extern __shared__ __align__(16) unsigned char smem[];

    const int tid  = threadIdx.x;
    const int wid  = tid >> 5;
    const int lane = tid & 31;
    const int warp_m = wid >> 2;          // 0..1
    const int warp_n = wid & 3;           // 0..3

    const int n0 = blockIdx.x * BN;
    const int m0 = blockIdx.y * BM;

    const uint32_t sb = smem_u32(smem);

    // ---- hoisted cp.async addressing --------------------------------------
    // tile = 128 rows x 8 x 16B segs; thread handles rows row0 + t*32, t=0..3
    const int row0 = tid >> 3;
    const int seg  = tid & 7;
    const uint32_t soff0 = (uint32_t)(row0 * ROW_BYTES + ((seg ^ (row0 & 7)) * 16));
    const __half* pA0 = g_X  + (size_t)(m0 + row0) * IN_F + seg * 8;
    const __half* pB0 = g_Wh + (size_t)(n0 + row0) * IN_F + seg * 8;

    auto issue_chunk = [&](int c, uint32_t abase) {
        const uint32_t bbase = abase + A_TILE_BYTES;
        const __half* pa = pA0 + c * BK;
        const __half* pb = pB0 + c * BK;
#pragma unroll
        for (int t = 0; t < 4; t++) {
            cp_async16(abase + soff0 + (uint32_t)(t * 32 * ROW_BYTES),
                       pa + (size_t)t * 32 * IN_F);
            cp_async16(bbase + soff0 + (uint32_t)(t * 32 * ROW_BYTES),
                       pb + (size_t)t * 32 * IN_F);
        }
    };

    // ---- ldmatrix per-lane addressing (XOR swizzle) -----------------------
    const uint32_t lxor  = (uint32_t)(lane & 7);
    const uint32_t a_base = (uint32_t)((warp_m * 64 + (lane & 15)) * ROW_BYTES);
    const uint32_t a_sel  = (uint32_t)(lane >> 4);
    const uint32_t b_base = (uint32_t)((warp_n * 32 + (lane & 7)
                                        + ((lane >> 4) & 1) * 8) * ROW_BYTES);
    const uint32_t b_sel  = (uint32_t)((lane >> 3) & 1);

    auto a_addr = [&](uint32_t As, int mt, int kk) {
        return As + a_base + (uint32_t)(mt * 16 * ROW_BYTES)
                  + ((((uint32_t)kk * 2 + a_sel) ^ lxor) * 16);
    };
    auto b_addr = [&](uint32_t Bs, int pr, int kk) {
        return Bs + b_base + (uint32_t)(pr * 16 * ROW_BYTES)
                  + ((((uint32_t)kk * 2 + b_sel) ^ lxor) * 16);
    };

    // Prologue: fill STAGES-1 stages
#pragma unroll
    for (int c = 0; c < STAGES - 1; c++) {
        issue_chunk(c, sb + (uint32_t)(c * STAGE_BYTES));
        CP_COMMIT();
    }

    float acc[4][4][4];
#pragma unroll
    for (int mt = 0; mt < 4; mt++)
#pragma unroll
        for (int nt = 0; nt < 4; nt++)
#pragma unroll
            for (int q = 0; q < 4; q++) acc[mt][nt][q] = 0.0f;

    uint32_t af[2][4][4];     // A double-buffered
    uint32_t bf[2][4];        // B single-buffered

    uint32_t stage = 0;       // current consume stage index
#pragma unroll 1
    for (int c = 0; c < NCHUNK; ++c) {
        CP_WAIT(STAGES - 2);
        __syncthreads();

        const uint32_t As = sb + stage * STAGE_BYTES;
        const uint32_t Bs = As + A_TILE_BYTES;

        // kk=0 A fragments; latency covered by issuing next chunk's cp.async
#pragma unroll
        for (int mt = 0; mt < 4; mt++) ldsm_x4(af[0][mt], a_addr(As, mt, 0));

        const int nk = c + STAGES - 1;
        if (nk < NCHUNK) {
            uint32_t wstage = stage + (STAGES - 1);
            if (wstage >= STAGES) wstage -= STAGES;
            issue_chunk(nk, sb + wstage * STAGE_BYTES);
        }
        CP_COMMIT();

#pragma unroll
        for (int kk = 0; kk < BK / 16; kk++) {        // 4 k16 steps
            const int cur = kk & 1;
            // B fragments for this kk (latency covered by A-next issues + MMAs)
#pragma unroll
            for (int pr = 0; pr < 2; pr++) ldsm_x4(&bf[pr][0], b_addr(Bs, pr, kk));
            if (kk < BK / 16 - 1) {                   // prefetch next A
#pragma unroll
                for (int mt = 0; mt < 4; mt++)
                    ldsm_x4(af[cur ^ 1][mt], a_addr(As, mt, kk + 1));
            }
#pragma unroll
            for (int nt = 0; nt < 4; nt++) {
                const uint32_t b0 = bf[nt >> 1][(nt & 1) * 2];
                const uint32_t b1 = bf[nt >> 1][(nt & 1) * 2 + 1];
#pragma unroll
                for (int mt = 0; mt < 4; mt++)
                    mma_f16(acc[mt][nt], af[cur][mt], b0, b1);
            }
        }

        if (++stage == STAGES) stage = 0;
    }

    // Epilogue: add bias, store float2 per (row, nt)
    const int qr = lane >> 2;
    const int qk = lane & 3;
#pragma unroll
    for (int mt = 0; mt < 4; mt++) {
        const int r = m0 + warp_m * 64 + mt * 16 + qr;
#pragma unroll
        for (int nt = 0; nt < 4; nt++) {
            const int col = n0 + warp_n * 32 + nt * 8 + 2 * qk;
            const float bx = __ldg(bias + col);
            const float by = __ldg(bias + col + 1);
            float2 v0 = make_float2(acc[mt][nt][0] + bx, acc[mt][nt][1] + by);
            float2 v1 = make_float2(acc[mt][nt][2] + bx, acc[mt][nt][3] + by);
            *reinterpret_cast<float2*>(Out + (size_t)r * OUT_F + col) = v0;
            *reinterpret_cast<float2*>(Out + (size_t)(r + 8) * OUT_F + col) = v1;
        }
    }
}

// ---------------------------------------------------------------------------
// Launch
// ---------------------------------------------------------------------------
extern "C" void kernel_launch(void* const* d_in, const int* in_sizes, int n_in,
                              void* d_out, int out_size) {
    const float* x    = (const float*)d_in[0];   // [8192, 4096] f32
    const float* w    = (const float*)d_in[1];   // [65536] f32
    const float* bias = (const float*)d_in[2];   // [4096] f32
    const int*   idx  = (const int*)d_in[3];     // [4096*4096] i32
    float* out = (float*)d_out;                  // [8192, 4096] f32

    static bool attr_set = false;
    if (!attr_set) {
        cudaFuncSetAttribute(hashed_gemm,
                             cudaFuncAttributeMaxDynamicSharedMemorySize, SMEM_BYTES);
        attr_set = true;
    }

    // Stage 1: convert X and gather/convert W in one overlapped launch.
    prep_operands<<<GX_BLOCKS + GW_BLOCKS, 256>>>(x, idx, w);

    // Stage 2: fp16 tensor-core GEMM + bias epilogue.
    dim3 grid(OUT_F / BN, TOKENS_N / BM);                    // (32, 64)
    hashed_gemm<<<grid, 256, SMEM_BYTES>>>(bias, out);
}

// round 15
// speedup vs baseline: 1.0849x; 1.0849x over previous
#include <cuda_runtime.h>
#include <cuda_fp16.h>
#include <cstdint>
#include <cstddef>

// Problem dims
#define TOKENS_N 8192
#define IN_F     4096
#define OUT_F    4096

// GEMM tiling: CTA 128x128, warp 64x32, BK=64 halves (128B/row)
#define BM      128
#define BN      128
#define BK      64
#define STAGES  3
#define NCHUNK  (IN_F / BK)            // 64

// smem: 128B rows with XOR swizzle (seg ^= row&7) -> conflict-free for both
// cp.async 16B stores and ldmatrix 8-row phases.
#define ROW_BYTES    128
#define A_TILE_BYTES (BM * ROW_BYTES)                 // 16384
#define B_TILE_BYTES (BN * ROW_BYTES)                 // 16384
#define STAGE_BYTES  (A_TILE_BYTES + B_TILE_BYTES)    // 32768
#define SMEM_BYTES   (STAGES * STAGE_BYTES)           // 98304 -> 2 CTAs/SM

// Pre-converted operands (device globals: allowed scratch)
__device__ __half g_X [(size_t)TOKENS_N * IN_F];   // 64 MB
__device__ __half g_Wh[(size_t)OUT_F   * IN_F];    // 32 MB

#define GX_BLOCKS ((unsigned)(((size_t)TOKENS_N * IN_F / 8) / 256))   // 16384
#define GW_BLOCKS ((unsigned)(((size_t)OUT_F   * IN_F / 8) / 256))    // 8192

// ---------------------------------------------------------------------------
// helpers
// ---------------------------------------------------------------------------
__device__ __forceinline__ uint32_t smem_u32(const void* p) {
    uint32_t a;
    asm("{ .reg .u64 t; cvta.to.shared.u64 t, %1; cvt.u32.u64 %0, t; }"
        : "=r"(a) : "l"(p));
    return a;
}

__device__ __forceinline__ void cp_async16(uint32_t dst, const void* src) {
    asm volatile("cp.async.cg.shared.global [%0], [%1], 16;" :: "r"(dst), "l"(src));
}
#define CP_COMMIT() asm volatile("cp.async.commit_group;" ::: "memory")
#define CP_WAIT(n)  asm volatile("cp.async.wait_group %0;" :: "n"(n) : "memory")

__device__ __forceinline__ void ldsm_x4(uint32_t* r, uint32_t addr) {
    asm volatile("ldmatrix.sync.aligned.m8n8.x4.shared.b16 {%0,%1,%2,%3}, [%4];"
        : "=r"(r[0]), "=r"(r[1]), "=r"(r[2]), "=r"(r[3]) : "r"(addr));
}

__device__ __forceinline__ void mma_f16(float* c, const uint32_t* a,
                                        uint32_t b0, uint32_t b1) {
    asm volatile(
        "mma.sync.aligned.m16n8k16.row.col.f32.f16.f16.f32 "
        "{%0,%1,%2,%3}, {%4,%5,%6,%7}, {%8,%9}, {%0,%1,%2,%3};"
        : "+f"(c[0]), "+f"(c[1]), "+f"(c[2]), "+f"(c[3])
        : "r"(a[0]), "r"(a[1]), "r"(a[2]), "r"(a[3]), "r"(b0), "r"(b1));
}

__device__ __forceinline__ uint32_t h2u(__half2 h) {
    return *reinterpret_cast<uint32_t*>(&h);
}

// ---------------------------------------------------------------------------
// Kernel 1 (merged): blocks [0, GX_BLOCKS) convert X fp32->fp16;
// blocks [GX_BLOCKS, ...) gather+convert W. Both DRAM-bound; overlapped.
// ---------------------------------------------------------------------------
__global__ void __launch_bounds__(256)
prep_operands(const float* __restrict__ x, const int* __restrict__ idx,
              const float* __restrict__ w) {
    unsigned b = blockIdx.x;
    if (b < GX_BLOCKS) {
        size_t i = (size_t)b * 256 + threadIdx.x;
        const float4* p = reinterpret_cast<const float4*>(x) + 2 * i;
        float4 a = p[0], c = p[1];
        uint4 o;
        o.x = h2u(__floats2half2_rn(a.x, a.y));
        o.y = h2u(__floats2half2_rn(a.z, a.w));
        o.z = h2u(__floats2half2_rn(c.x, c.y));
        o.w = h2u(__floats2half2_rn(c.z, c.w));
        reinterpret_cast<uint4*>(g_X)[i] = o;
    } else {
        size_t i = (size_t)(b - GX_BLOCKS) * 256 + threadIdx.x;
        const int4* ip = reinterpret_cast<const int4*>(idx) + 2 * i;
        int4 v0 = ip[0], v1 = ip[1];
        uint4 o;
        o.x = h2u(__floats2half2_rn(__ldg(w + v0.x), __ldg(w + v0.y)));
        o.y = h2u(__floats2half2_rn(__ldg(w + v0.z), __ldg(w + v0.w)));
        o.z = h2u(__floats2half2_rn(__ldg(w + v1.x), __ldg(w + v1.y)));
        o.w = h2u(__floats2half2_rn(__ldg(w + v1.z), __ldg(w + v1.w)));
        reinterpret_cast<uint4*>(g_Wh)[i] = o;
    }
}

// ---------------------------------------------------------------------------
// Kernel 2: fp16 mma.sync GEMM  Out[m,n] = sum_k X[m,k]*W[n,k] + bias[n]
// 256 threads = 8 warps, 2(M) x 4(N), warp tile 64x32. 3-stage cp.async.
// Fragments double-buffered; wait/barrier + next-chunk kk0 ldsm moved under
// the previous chunk's last MMA block (cross-chunk software pipelining).
// ---------------------------------------------------------------------------
extern "C" __global__ void __launch_bounds__(256, 2)
hashed_gemm(const float* __restrict__ bias, float* __restrict__ Out) {
    extern __shared__ __align__(16) unsigned char smem[];

    const int tid  = threadIdx.x;
    const int wid  = tid >> 5;
    const int lane = tid & 31;
    const int warp_m = wid >> 2;          // 0..1
    const int warp_n = wid & 3;           // 0..3

    const int n0 = blockIdx.x * BN;
    const int m0 = blockIdx.y * BM;

    const uint32_t sb = smem_u32(smem);

    // ---- hoisted cp.async addressing --------------------------------------
    const int row0 = tid >> 3;
    const int seg  = tid & 7;
    const uint32_t soff0 = (uint32_t)(row0 * ROW_BYTES + ((seg ^ (row0 & 7)) * 16));
    const __half* pA0 = g_X  + (size_t)(m0 + row0) * IN_F + seg * 8;
    const __half* pB0 = g_Wh + (size_t)(n0 + row0) * IN_F + seg * 8;

    auto issue_chunk = [&](int c, uint32_t abase) {
        const uint32_t bbase = abase + A_TILE_BYTES;
        const __half* pa = pA0 + c * BK;
        const __half* pb = pB0 + c * BK;
#pragma unroll
        for (int t = 0; t < 4; t++) {
            cp_async16(abase + soff0 + (uint32_t)(t * 32 * ROW_BYTES),
                       pa + (size_t)t * 32 * IN_F);
            cp_async16(bbase + soff0 + (uint32_t)(t * 32 * ROW_BYTES),
                       pb + (size_t)t * 32 * IN_F);
        }
    };

    // ---- ldmatrix per-lane addressing (XOR swizzle) -----------------------
    const uint32_t lxor   = (uint32_t)(lane & 7);
    const uint32_t a_base = (uint32_t)((warp_m * 64 + (lane & 15)) * ROW_BYTES);
    const uint32_t a_sel  = (uint32_t)(lane >> 4);
    const uint32_t b_base = (uint32_t)((warp_n * 32 + (lane & 7)
                                        + ((lane >> 4) & 1) * 8) * ROW_BYTES);
    const uint32_t b_sel  = (uint32_t)((lane >> 3) & 1);

    auto a_addr = [&](uint32_t stage_base, int mt, int kk) {
        return stage_base + a_base + (uint32_t)(mt * 16 * ROW_BYTES)
                  + ((((uint32_t)kk * 2 + a_sel) ^ lxor) * 16);
    };
    auto b_addr = [&](uint32_t stage_base, int pr, int kk) {
        return stage_base + A_TILE_BYTES + b_base + (uint32_t)(pr * 16 * ROW_BYTES)
                  + ((((uint32_t)kk * 2 + b_sel) ^ lxor) * 16);
    };

    float acc[4][4][4];
#pragma unroll
    for (int mt = 0; mt < 4; mt++)
#pragma unroll
        for (int nt = 0; nt < 4; nt++)
#pragma unroll
            for (int q = 0; q < 4; q++) acc[mt][nt][q] = 0.0f;

    uint32_t af[2][4][4];
    uint32_t bf[2][2][4];

    // Stage base rotation: cur = chunk c, nxt = chunk c+1, wrt = chunk c+2
    uint32_t cur_base = sb;
    uint32_t nxt_base = sb + STAGE_BYTES;
    uint32_t wrt_base = sb + 2 * STAGE_BYTES;

    // Prologue: issue chunks 0 and 1; wait chunk 0; load its kk=0 fragments.
    issue_chunk(0, cur_base); CP_COMMIT();
    issue_chunk(1, nxt_base); CP_COMMIT();
    CP_WAIT(1);
    __syncthreads();
#pragma unroll
    for (int mt = 0; mt < 4; mt++) ldsm_x4(af[0][mt], a_addr(cur_base, mt, 0));
#pragma unroll
    for (int pr = 0; pr < 2; pr++) ldsm_x4(bf[0][pr], b_addr(cur_base, pr, 0));

#pragma unroll 1
    for (int c = 0; c < NCHUNK; ++c) {
        if (c + 2 < NCHUNK) issue_chunk(c + 2, wrt_base);
        CP_COMMIT();   // empty commits at the tail keep group accounting uniform

#pragma unroll
        for (int kk = 0; kk < BK / 16; kk++) {        // 4 k16 steps
            const int cur = kk & 1;
            const int nxt = cur ^ 1;
            if (kk < BK / 16 - 1) {
                // prefetch kk+1 fragments from current stage
#pragma unroll
                for (int mt = 0; mt < 4; mt++)
                    ldsm_x4(af[nxt][mt], a_addr(cur_base, mt, kk + 1));
#pragma unroll
                for (int pr = 0; pr < 2; pr++)
                    ldsm_x4(bf[nxt][pr], b_addr(cur_base, pr, kk + 1));
            } else if (c + 1 < NCHUNK) {
                // chunk boundary moved here: wait next stage, barrier, then
                // prefetch NEXT chunk's kk=0 fragments; kk=3 MMAs hide it all.
                CP_WAIT(1);
                __syncthreads();
#pragma unroll
                for (int mt = 0; mt < 4; mt++)
                    ldsm_x4(af[nxt][mt], a_addr(nxt_base, mt, 0));
#pragma unroll
                for (int pr = 0; pr < 2; pr++)
                    ldsm_x4(bf[nxt][pr], b_addr(nxt_base, pr, 0));
            }
#pragma unroll
            for (int nt = 0; nt < 4; nt++) {
                const uint32_t b0 = bf[cur][nt >> 1][(nt & 1) * 2];
                const uint32_t b1 = bf[cur][nt >> 1][(nt & 1) * 2 + 1];
#pragma unroll
                for (int mt = 0; mt < 4; mt++)
                    mma_f16(acc[mt][nt], af[cur][mt], b0, b1);
            }
        }

        // rotate stages
        const uint32_t t = cur_base;
        cur_base = nxt_base;
        nxt_base = wrt_base;
        wrt_base = t;
    }

    // Epilogue: add bias, store float2 per (row, nt)
    const int qr = lane >> 2;
    const int qk = lane & 3;
#pragma unroll
    for (int mt = 0; mt < 4; mt++) {
        const int r = m0 + warp_m * 64 + mt * 16 + qr;
#pragma unroll
        for (int nt = 0; nt < 4; nt++) {
            const int col = n0 + warp_n * 32 + nt * 8 + 2 * qk;
            const float bx = __ldg(bias + col);
            const float by = __ldg(bias + col + 1);
            float2 v0 = make_float2(acc[mt][nt][0] + bx, acc[mt][nt][1] + by);
            float2 v1 = make_float2(acc[mt][nt][2] + bx, acc[mt][nt][3] + by);
            *reinterpret_cast<float2*>(Out + (size_t)r * OUT_F + col) = v0;
            *reinterpret_cast<float2*>(Out + (size_t)(r + 8) * OUT_F + col) = v1;
        }
    }
}

// ---------------------------------------------------------------------------
// Launch
// ---------------------------------------------------------------------------
extern "C" void kernel_launch(void* const* d_in, const int* in_sizes, int n_in,
                              void* d_out, int out_size) {
    const float* x    = (const float*)d_in[0];   // [8192, 4096] f32
    const float* w    = (const float*)d_in[1];   // [65536] f32
    const float* bias = (const float*)d_in[2];   // [4096] f32
    const int*   idx  = (const int*)d_in[3];     // [4096*4096] i32
    float* out = (float*)d_out;                  // [8192, 4096] f32

    static bool attr_set = false;
    if (!attr_set) {
        cudaFuncSetAttribute(hashed_gemm,
                             cudaFuncAttributeMaxDynamicSharedMemorySize, SMEM_BYTES);
        attr_set = true;
    }

    // Stage 1: convert X and gather/convert W in one overlapped launch.
    prep_operands<<<GX_BLOCKS + GW_BLOCKS, 256>>>(x, idx, w);

    // Stage 2: fp16 tensor-core GEMM + bias epilogue.
    dim3 grid(OUT_F / BN, TOKENS_N / BM);                    // (32, 64)
    hashed_gemm<<<grid, 256, SMEM_BYTES>>>(bias, out);
}

// round 16
// speedup vs baseline: 1.1281x; 1.0398x over previous
#include <cuda_runtime.h>
#include <cuda_fp16.h>
#include <cstdint>
#include <cstddef>

// Problem dims
#define TOKENS_N 8192
#define IN_F     4096
#define OUT_F    4096

// GEMM tiling: CTA 128x256, warp 64x64, BK=64 halves (128B/row)
#define BM      128
#define BN      256
#define BK      64
#define STAGES  3
#define NCHUNK  (IN_F / BK)            // 64

// smem: 128B rows with XOR swizzle (seg ^= row&7) -> conflict-free for both
// cp.async 16B stores and ldmatrix 8-row phases.
#define ROW_BYTES    128
#define A_TILE_BYTES (BM * ROW_BYTES)                 // 16384
#define B_TILE_BYTES (BN * ROW_BYTES)                 // 32768
#define STAGE_BYTES  (A_TILE_BYTES + B_TILE_BYTES)    // 49152
#define SMEM_BYTES   (STAGES * STAGE_BYTES)           // 147456 -> 1 CTA/SM

// Pre-converted operands (device globals: allowed scratch)
__device__ __half g_X [(size_t)TOKENS_N * IN_F];   // 64 MB
__device__ __half g_Wh[(size_t)OUT_F   * IN_F];    // 32 MB

#define GX_BLOCKS ((unsigned)(((size_t)TOKENS_N * IN_F / 8) / 256))   // 16384
#define GW_BLOCKS ((unsigned)(((size_t)OUT_F   * IN_F / 8) / 256))    // 8192

// ---------------------------------------------------------------------------
// helpers
// ---------------------------------------------------------------------------
__device__ __forceinline__ uint32_t smem_u32(const void* p) {
    uint32_t a;
    asm("{ .reg .u64 t; cvta.to.shared.u64 t, %1; cvt.u32.u64 %0, t; }"
        : "=r"(a) : "l"(p));
    return a;
}

__device__ __forceinline__ void cp_async16(uint32_t dst, const void* src) {
    asm volatile("cp.async.cg.shared.global [%0], [%1], 16;" :: "r"(dst), "l"(src));
}
#define CP_COMMIT() asm volatile("cp.async.commit_group;" ::: "memory")
#define CP_WAIT(n)  asm volatile("cp.async.wait_group %0;" :: "n"(n) : "memory")

__device__ __forceinline__ void ldsm_x4(uint32_t* r, uint32_t addr) {
    asm volatile("ldmatrix.sync.aligned.m8n8.x4.shared.b16 {%0,%1,%2,%3}, [%4];"
        : "=r"(r[0]), "=r"(r[1]), "=r"(r[2]), "=r"(r[3]) : "r"(addr));
}

__device__ __forceinline__ void mma_f16(float* c, const uint32_t* a,
                                        uint32_t b0, uint32_t b1) {
    asm volatile(
        "mma.sync.aligned.m16n8k16.row.col.f32.f16.f16.f32 "
        "{%0,%1,%2,%3}, {%4,%5,%6,%7}, {%8,%9}, {%0,%1,%2,%3};"
        : "+f"(c[0]), "+f"(c[1]), "+f"(c[2]), "+f"(c[3])
        : "r"(a[0]), "r"(a[1]), "r"(a[2]), "r"(a[3]), "r"(b0), "r"(b1));
}

__device__ __forceinline__ uint32_t h2u(__half2 h) {
    return *reinterpret_cast<uint32_t*>(&h);
}

// ---------------------------------------------------------------------------
// Kernel 1 (merged): blocks [0, GX_BLOCKS) convert X fp32->fp16;
// blocks [GX_BLOCKS, ...) gather+convert W. Both DRAM-bound; overlapped.
// ---------------------------------------------------------------------------
__global__ void __launch_bounds__(256)
prep_operands(const float* __restrict__ x, const int* __restrict__ idx,
              const float* __restrict__ w) {
    unsigned b = blockIdx.x;
    if (b < GX_BLOCKS) {
        size_t i = (size_t)b * 256 + threadIdx.x;
        const float4* p = reinterpret_cast<const float4*>(x) + 2 * i;
        float4 a = p[0], c = p[1];
        uint4 o;
        o.x = h2u(__floats2half2_rn(a.x, a.y));
        o.y = h2u(__floats2half2_rn(a.z, a.w));
        o.z = h2u(__floats2half2_rn(c.x, c.y));
        o.w = h2u(__floats2half2_rn(c.z, c.w));
        reinterpret_cast<uint4*>(g_X)[i] = o;
    } else {
        size_t i = (size_t)(b - GX_BLOCKS) * 256 + threadIdx.x;
        const int4* ip = reinterpret_cast<const int4*>(idx) + 2 * i;
        int4 v0 = ip[0], v1 = ip[1];
        uint4 o;
        o.x = h2u(__floats2half2_rn(__ldg(w + v0.x), __ldg(w + v0.y)));
        o.y = h2u(__floats2half2_rn(__ldg(w + v0.z), __ldg(w + v0.w)));
        o.z = h2u(__floats2half2_rn(__ldg(w + v1.x), __ldg(w + v1.y)));
        o.w = h2u(__floats2half2_rn(__ldg(w + v1.z), __ldg(w + v1.w)));
        reinterpret_cast<uint4*>(g_Wh)[i] = o;
    }
}

// ---------------------------------------------------------------------------
// Kernel 2: fp16 mma.sync GEMM  Out[m,n] = sum_k X[m,k]*W[n,k] + bias[n]
// 256 threads = 8 warps, 2(M) x 4(N), warp tile 64x64 (halves smem bytes/MAC
// vs 64x32 -> gets under the 128 B/cyc crossbar). 3-stage cp.async with
// cross-chunk software pipelining (wait/barrier hidden under last MMA block).
// A fragments double-buffered, B single-buffered.
// ---------------------------------------------------------------------------
extern "C" __global__ void __launch_bounds__(256, 1)
hashed_gemm(const float* __restrict__ bias, float* __restrict__ Out) {
    extern __shared__ __align__(16) unsigned char smem[];

    const int tid  = threadIdx.x;
    const int wid  = tid >> 5;
    const int lane = tid & 31;
    const int warp_m = wid & 1;           // 0..1 (64 M rows)
    const int warp_n = wid >> 1;          // 0..3 (64 N cols)

    const int n0 = blockIdx.x * BN;
    const int m0 = blockIdx.y * BM;

    const uint32_t sb = smem_u32(smem);

    // ---- hoisted cp.async addressing --------------------------------------
    const int row0 = tid >> 3;            // 0..31
    const int seg  = tid & 7;
    const uint32_t soff0 = (uint32_t)(row0 * ROW_BYTES + ((seg ^ (row0 & 7)) * 16));
    const __half* pA0 = g_X  + (size_t)(m0 + row0) * IN_F + seg * 8;
    const __half* pB0 = g_Wh + (size_t)(n0 + row0) * IN_F + seg * 8;

    auto issue_chunk = [&](int c, uint32_t abase) {
        const uint32_t bbase = abase + A_TILE_BYTES;
        const __half* pa = pA0 + c * BK;
        const __half* pb = pB0 + c * BK;
#pragma unroll
        for (int t = 0; t < 4; t++) {          // A: 128 rows
            cp_async16(abase + soff0 + (uint32_t)(t * 32 * ROW_BYTES),
                       pa + (size_t)t * 32 * IN_F);
        }
#pragma unroll
        for (int t = 0; t < 8; t++) {          // B: 256 rows
            cp_async16(bbase + soff0 + (uint32_t)(t * 32 * ROW_BYTES),
                       pb + (size_t)t * 32 * IN_F);
        }
    };

    // ---- ldmatrix per-lane addressing (XOR swizzle) -----------------------
    const uint32_t lxor   = (uint32_t)(lane & 7);
    const uint32_t a_base = (uint32_t)((warp_m * 64 + (lane & 15)) * ROW_BYTES);
    const uint32_t a_sel  = (uint32_t)(lane >> 4);
    const uint32_t b_base = (uint32_t)((warp_n * 64 + (lane & 7)
                                        + ((lane >> 4) & 1) * 8) * ROW_BYTES);
    const uint32_t b_sel  = (uint32_t)((lane >> 3) & 1);

    auto a_addr = [&](uint32_t stage_base, int mt, int kk) {
        return stage_base + a_base + (uint32_t)(mt * 16 * ROW_BYTES)
                  + ((((uint32_t)kk * 2 + a_sel) ^ lxor) * 16);
    };
    auto b_addr = [&](uint32_t stage_base, int pr, int kk) {
        return stage_base + A_TILE_BYTES + b_base + (uint32_t)(pr * 16 * ROW_BYTES)
                  + ((((uint32_t)kk * 2 + b_sel) ^ lxor) * 16);
    };

    float acc[4][8][4];
#pragma unroll
    for (int mt = 0; mt < 4; mt++)
#pragma unroll
        for (int nt = 0; nt < 8; nt++)
#pragma unroll
            for (int q = 0; q < 4; q++) acc[mt][nt][q] = 0.0f;

    uint32_t af[2][4][4];   // A double-buffered
    uint32_t bf[4][4];      // B single-buffered (reloaded each kk)

    // Stage base rotation: cur = chunk c, nxt = chunk c+1, wrt = chunk c+2
    uint32_t cur_base = sb;
    uint32_t nxt_base = sb + STAGE_BYTES;
    uint32_t wrt_base = sb + 2 * STAGE_BYTES;

    // Prologue: issue chunks 0 and 1; wait chunk 0; load its kk=0 A fragments.
    issue_chunk(0, cur_base); CP_COMMIT();
    issue_chunk(1, nxt_base); CP_COMMIT();
    CP_WAIT(1);
    __syncthreads();
#pragma unroll
    for (int mt = 0; mt < 4; mt++) ldsm_x4(af[0][mt], a_addr(cur_base, mt, 0));

#pragma unroll 1
    for (int c = 0; c < NCHUNK; ++c) {
        if (c + 2 < NCHUNK) issue_chunk(c + 2, wrt_base);
        CP_COMMIT();   // empty commits at the tail keep group accounting uniform

#pragma unroll
        for (int kk = 0; kk < BK / 16; kk++) {        // 4 k16 steps
            const int cur = kk & 1;
            const int nxt = cur ^ 1;
            // B fragments for this kk (latency covered by A prefetch + MMAs)
#pragma unroll
            for (int pr = 0; pr < 4; pr++)
                ldsm_x4(bf[pr], b_addr(cur_base, pr, kk));
            if (kk < BK / 16 - 1) {
#pragma unroll
                for (int mt = 0; mt < 4; mt++)
                    ldsm_x4(af[nxt][mt], a_addr(cur_base, mt, kk + 1));
            } else if (c + 1 < NCHUNK) {
                // chunk boundary: wait next stage, barrier, then prefetch the
                // NEXT chunk's kk=0 A fragments; kk=3's 32 MMAs hide it all.
                CP_WAIT(1);
                __syncthreads();
#pragma unroll
                for (int mt = 0; mt < 4; mt++)
                    ldsm_x4(af[nxt][mt], a_addr(nxt_base, mt, 0));
            }
#pragma unroll
            for (int nt = 0; nt < 8; nt++) {
                const uint32_t b0 = bf[nt >> 1][(nt & 1) * 2];
                const uint32_t b1 = bf[nt >> 1][(nt & 1) * 2 + 1];
#pragma unroll
                for (int mt = 0; mt < 4; mt++)
                    mma_f16(acc[mt][nt], af[cur][mt], b0, b1);
            }
        }

        // rotate stages
        const uint32_t t = cur_base;
        cur_base = nxt_base;
        nxt_base = wrt_base;
        wrt_base = t;
    }

    // Epilogue: add bias, store float2 per (row, nt)
    const int qr = lane >> 2;
    const int qk = lane & 3;
#pragma unroll
    for (int mt = 0; mt < 4; mt++) {
        const int r = m0 + warp_m * 64 + mt * 16 + qr;
#pragma unroll
        for (int nt = 0; nt < 8; nt++) {
            const int col = n0 + warp_n * 64 + nt * 8 + 2 * qk;
            const float bx = __ldg(bias + col);
            const float by = __ldg(bias + col + 1);
            float2 v0 = make_float2(acc[mt][nt][0] + bx, acc[mt][nt][1] + by);
            float2 v1 = make_float2(acc[mt][nt][2] + bx, acc[mt][nt][3] + by);
            *reinterpret_cast<float2*>(Out + (size_t)r * OUT_F + col) = v0;
            *reinterpret_cast<float2*>(Out + (size_t)(r + 8) * OUT_F + col) = v1;
        }
    }
}

// ---------------------------------------------------------------------------
// Launch
// ---------------------------------------------------------------------------
extern "C" void kernel_launch(void* const* d_in, const int* in_sizes, int n_in,
                              void* d_out, int out_size) {
    const float* x    = (const float*)d_in[0];   // [8192, 4096] f32
    const float* w    = (const float*)d_in[1];   // [65536] f32
    const float* bias = (const float*)d_in[2];   // [4096] f32
    const int*   idx  = (const int*)d_in[3];     // [4096*4096] i32
    float* out = (float*)d_out;                  // [8192, 4096] f32

    static bool attr_set = false;
    if (!attr_set) {
        cudaFuncSetAttribute(hashed_gemm,
                             cudaFuncAttributeMaxDynamicSharedMemorySize, SMEM_BYTES);
        attr_set = true;
    }

    // Stage 1: convert X and gather/convert W in one overlapped launch.
    prep_operands<<<GX_BLOCKS + GW_BLOCKS, 256>>>(x, idx, w);

    // Stage 2: fp16 tensor-core GEMM + bias epilogue.
    dim3 grid(OUT_F / BN, TOKENS_N / BM);                    // (16, 64)
    hashed_gemm<<<grid, 256, SMEM_BYTES>>>(bias, out);
}